// round 1
// baseline (speedup 1.0000x reference)
#include <cuda_runtime.h>
#include <math.h>

#define NB 512
#define DMODEL 2048
#define NH 8
#define DMEM 128
#define NM 512
#define KPROJ_N 1024     // H*DMEM
#define VPROJ_N 2048     // 2*H*DMEM
#define MEM_ELEMS (NB*NM*DMEM)   // 33554432

// Scratch (device globals: no allocation allowed)
__device__ float g_ak[NB * KPROJ_N];        // act(key @ W_key + b_key), (B, H*128)
__device__ float g_v [NB * VPROJ_N];        // values @ W_val + b_val,   (B, H*256)
__device__ float g_aq[NM * DMEM];           // act(addresses)
__device__ float g_si[NM * DMEM];           // sigmoid(interpolation_logits)
__device__ float g_S [NB * NM * NH];        // S[b,m,h] = sum_d aq[m,d]*ak[b,h,d]

__device__ __forceinline__ float actf(float x) {
    // elu(x)+1 = x+1 (x>0) else exp(x)
    return x > 0.f ? x + 1.f : __expf(x);
}
__device__ __forceinline__ float sigm(float x) {
    return 1.f / (1.f + __expf(-x));
}

// ---------------------------------------------------------------------------
// K0: aq = act(addresses), si = sigmoid(interpolation_logits)   (64K elems)
// ---------------------------------------------------------------------------
__global__ void prep_kernel(const float* __restrict__ addresses,
                            const float* __restrict__ interp) {
    int i = blockIdx.x * blockDim.x + threadIdx.x;
    if (i < NM * DMEM) {
        g_aq[i] = actf(addresses[i]);
        g_si[i] = sigm(interp[i]);
    }
}

// ---------------------------------------------------------------------------
// K1: fused projection GEMMs (fp32, 64x64x16 tiles, 128 threads, 8x4/thread)
//   blockIdx.x <  16: C=g_ak = act(key @ W_key + b_key),   N=1024
//   blockIdx.x >= 16: C=g_v  =      values @ W_val + b_val, N=2048
// ---------------------------------------------------------------------------
__global__ __launch_bounds__(128) void proj_kernel(
    const float* __restrict__ key, const float* __restrict__ values,
    const float* __restrict__ W_key, const float* __restrict__ b_key,
    const float* __restrict__ W_val, const float* __restrict__ b_val)
{
    const float *A, *W, *bias;
    float* C;
    int N, act;
    int bx = blockIdx.x;
    if (bx < KPROJ_N / 64) { A = key;    W = W_key; bias = b_key; C = g_ak; N = KPROJ_N; act = 1; }
    else { bx -= KPROJ_N / 64; A = values; W = W_val; bias = b_val; C = g_v;  N = VPROJ_N; act = 0; }

    __shared__ float As[16][64];   // As[k][m]
    __shared__ float Bs[16][64];   // Bs[k][n]

    int tid = threadIdx.x;
    int bm0 = blockIdx.y * 64;
    int bn0 = bx * 64;
    int tx = tid & 15;             // n-tile: 4 cols
    int ty = tid >> 4;             // m-tile: 8 rows

    float acc[8][4];
    #pragma unroll
    for (int i = 0; i < 8; i++)
        #pragma unroll
        for (int j = 0; j < 4; j++) acc[i][j] = 0.f;

    float4 aR[2], bR[2];
    #pragma unroll
    for (int i = 0; i < 2; i++) {
        int idx = tid + i * 128;
        aR[i] = *(const float4*)(A + (bm0 + (idx >> 2)) * DMODEL + (idx & 3) * 4);
        bR[i] = *(const float4*)(W + (idx >> 4) * N + bn0 + (idx & 15) * 4);
    }

    const int NKT = DMODEL / 16;   // 128
    for (int kt = 0; kt < NKT; kt++) {
        __syncthreads();
        #pragma unroll
        for (int i = 0; i < 2; i++) {
            int idx = tid + i * 128;
            int ar = idx >> 2, ac = (idx & 3) * 4;
            As[ac + 0][ar] = aR[i].x;
            As[ac + 1][ar] = aR[i].y;
            As[ac + 2][ar] = aR[i].z;
            As[ac + 3][ar] = aR[i].w;
            int br = idx >> 4, bc = (idx & 15) * 4;
            *(float4*)&Bs[br][bc] = bR[i];
        }
        __syncthreads();
        if (kt + 1 < NKT) {
            int k0 = (kt + 1) * 16;
            #pragma unroll
            for (int i = 0; i < 2; i++) {
                int idx = tid + i * 128;
                aR[i] = *(const float4*)(A + (bm0 + (idx >> 2)) * DMODEL + k0 + (idx & 3) * 4);
                bR[i] = *(const float4*)(W + (k0 + (idx >> 4)) * N + bn0 + (idx & 15) * 4);
            }
        }
        #pragma unroll
        for (int k = 0; k < 16; k++) {
            float4 a0 = *(const float4*)&As[k][ty * 8];
            float4 a1 = *(const float4*)&As[k][ty * 8 + 4];
            float4 b0 = *(const float4*)&Bs[k][tx * 4];
            float av[8] = {a0.x, a0.y, a0.z, a0.w, a1.x, a1.y, a1.z, a1.w};
            float bv[4] = {b0.x, b0.y, b0.z, b0.w};
            #pragma unroll
            for (int i = 0; i < 8; i++)
                #pragma unroll
                for (int j = 0; j < 4; j++)
                    acc[i][j] = fmaf(av[i], bv[j], acc[i][j]);
        }
    }

    float4 bvv = *(const float4*)(bias + bn0 + tx * 4);
    float bb[4] = {bvv.x, bvv.y, bvv.z, bvv.w};
    #pragma unroll
    for (int i = 0; i < 8; i++) {
        float4 o;
        o.x = acc[i][0] + bb[0];
        o.y = acc[i][1] + bb[1];
        o.z = acc[i][2] + bb[2];
        o.w = acc[i][3] + bb[3];
        if (act) { o.x = actf(o.x); o.y = actf(o.y); o.z = actf(o.z); o.w = actf(o.w); }
        *(float4*)(C + (bm0 + ty * 8 + i) * N + bn0 + tx * 4) = o;
    }
}

// ---------------------------------------------------------------------------
// K2: S[b,m,h] = sum_d aq[m,d] * ak[b,h,d]
//   grid (M/32, B), 256 threads: each thread one (m,h)
// ---------------------------------------------------------------------------
__global__ __launch_bounds__(256) void s_kernel() {
    int b  = blockIdx.y;
    int m0 = blockIdx.x * 32;
    __shared__ float ak_s[8][132];   // padded stride, /4 aligned
    __shared__ float aq_s[32][132];
    int t = threadIdx.x;
    {
        int h = t >> 5, d4 = (t & 31) * 4;
        float4 v = *(const float4*)&g_ak[b * KPROJ_N + h * DMEM + d4];
        *(float4*)&ak_s[h][d4] = v;
    }
    #pragma unroll
    for (int i = 0; i < 4; i++) {
        int idx = t + i * 256;
        int ml = idx >> 5, d4 = (idx & 31) * 4;
        float4 v = *(const float4*)&g_aq[(m0 + ml) * DMEM + d4];
        *(float4*)&aq_s[ml][d4] = v;
    }
    __syncthreads();
    int ml = t >> 3, h = t & 7;
    float s = 0.f;
    #pragma unroll
    for (int d4 = 0; d4 < 32; d4++) {
        float4 a = *(const float4*)&aq_s[ml][d4 * 4];
        float4 k = *(const float4*)&ak_s[h][d4 * 4];
        s += a.x * k.x + a.y * k.y + a.z * k.z + a.w * k.w;
    }
    g_S[(b * NM + m0 + ml) * NH + h] = s;
}

// ---------------------------------------------------------------------------
// K3: epilogue (memory-bound): for each (b,m,d):
//   num_u = sum_h S*v[h][d], num_l = sum_h S*v[h][128+d], denom = sum_h S + 1e-5
//   wf = 0.7*sigmoid(num_l/denom)*si[m,d]
//   next_mem = mem + wf*(num_u/denom - mem); next_mass = wm + wf  (mask aware)
//   grid (M/8, B), 256 threads: thread = (ml = t>>5, d4 = t&31) -> one float4
// ---------------------------------------------------------------------------
__global__ __launch_bounds__(256) void epilogue_kernel(
    const float* __restrict__ memories, const float* __restrict__ write_mass,
    const unsigned char* __restrict__ batch_mask, float* __restrict__ out)
{
    int b  = blockIdx.y;
    int m0 = blockIdx.x * 8;
    __shared__ float4 v_s[NH * 64];    // v[h][e4], e4 in [0,64)
    __shared__ float  S_s[8][8];
    int t = threadIdx.x;
    #pragma unroll
    for (int i = 0; i < 2; i++) {
        int idx = t + i * 256;
        v_s[idx] = ((const float4*)(g_v + (size_t)b * VPROJ_N))[idx];
    }
    if (t < 64)
        S_s[t >> 3][t & 7] = g_S[((size_t)b * NM + m0) * NH + t];
    __syncthreads();

    int ml = t >> 5, d4 = t & 31;
    int m  = m0 + ml;

    float S[8];
    float denom = 1e-5f;
    #pragma unroll
    for (int h = 0; h < 8; h++) { S[h] = S_s[ml][h]; denom += S[h]; }
    float rd = __fdividef(1.f, denom);

    float4 aU = {0, 0, 0, 0}, aL = {0, 0, 0, 0};
    #pragma unroll
    for (int h = 0; h < 8; h++) {
        float s = S[h];
        float4 vu = v_s[h * 64 + d4];
        float4 vl = v_s[h * 64 + 32 + d4];
        aU.x = fmaf(s, vu.x, aU.x); aU.y = fmaf(s, vu.y, aU.y);
        aU.z = fmaf(s, vu.z, aU.z); aU.w = fmaf(s, vu.w, aU.w);
        aL.x = fmaf(s, vl.x, aL.x); aL.y = fmaf(s, vl.y, aL.y);
        aL.z = fmaf(s, vl.z, aL.z); aL.w = fmaf(s, vl.w, aL.w);
    }
    float4 upd = {aU.x * rd, aU.y * rd, aU.z * rd, aU.w * rd};
    float4 wl  = {aL.x * rd, aL.y * rd, aL.z * rd, aL.w * rd};

    float4 si = *(const float4*)&g_si[m * DMEM + d4 * 4];
    float4 wf;
    wf.x = 0.7f * sigm(wl.x) * si.x;
    wf.y = 0.7f * sigm(wl.y) * si.y;
    wf.z = 0.7f * sigm(wl.z) * si.z;
    wf.w = 0.7f * sigm(wl.w) * si.w;

    size_t base = ((size_t)b * NM + m) * DMEM + d4 * 4;
    float4 mem = *(const float4*)&memories[base];
    float4 wm  = *(const float4*)&write_mass[base];

    float4 om, oa;
    if (batch_mask[b]) {
        om = mem; oa = wm;
    } else {
        om.x = mem.x + wf.x * (upd.x - mem.x);
        om.y = mem.y + wf.y * (upd.y - mem.y);
        om.z = mem.z + wf.z * (upd.z - mem.z);
        om.w = mem.w + wf.w * (upd.w - mem.w);
        oa.x = wm.x + wf.x; oa.y = wm.y + wf.y;
        oa.z = wm.z + wf.z; oa.w = wm.w + wf.w;
    }
    *(float4*)&out[base] = om;
    *(float4*)&out[MEM_ELEMS + base] = oa;
}

// ---------------------------------------------------------------------------
extern "C" void kernel_launch(void* const* d_in, const int* in_sizes, int n_in,
                              void* d_out, int out_size) {
    const float* key        = (const float*)d_in[0];
    const float* values     = (const float*)d_in[1];
    const float* memories   = (const float*)d_in[2];
    const float* write_mass = (const float*)d_in[3];
    const unsigned char* batch_mask = (const unsigned char*)d_in[4];
    const float* W_key      = (const float*)d_in[5];
    const float* b_key      = (const float*)d_in[6];
    const float* W_val      = (const float*)d_in[7];
    const float* b_val      = (const float*)d_in[8];
    const float* addresses  = (const float*)d_in[9];
    const float* interp     = (const float*)d_in[10];
    float* out = (float*)d_out;

    prep_kernel<<<256, 256>>>(addresses, interp);
    proj_kernel<<<dim3((KPROJ_N + VPROJ_N) / 64, NB / 64), 128>>>(
        key, values, W_key, b_key, W_val, b_val);
    s_kernel<<<dim3(NM / 32, NB), 256>>>();
    epilogue_kernel<<<dim3(NM / 8, NB), 256>>>(memories, write_mass, batch_mask, out);
}

// round 6
// speedup vs baseline: 1.3623x; 1.3623x over previous
#include <cuda_runtime.h>
#include <math.h>

#define NB 512
#define DMODEL 2048
#define NH 8
#define DMEM 128
#define NM 512
#define KPROJ_N 1024     // H*DMEM
#define VPROJ_N 2048     // 2*H*DMEM
#define MEM_ELEMS (NB*NM*DMEM)

// Scratch (device globals: no allocation allowed)
__device__ float g_ak[NB * KPROJ_N];
__device__ float g_v [NB * VPROJ_N];
__device__ float g_aq[NM * DMEM];
__device__ float g_si[NM * DMEM];
__device__ float g_S [NB * NM * NH];

__device__ __forceinline__ float actf(float x) {
    return x > 0.f ? x + 1.f : __expf(x);   // elu(x)+1
}
__device__ __forceinline__ float sigm(float x) {
    return 1.f / (1.f + __expf(-x));
}
__device__ __forceinline__ unsigned f2tf32(float x) {
    unsigned r; asm("cvt.rna.tf32.f32 %0, %1;" : "=r"(r) : "f"(x)); return r;
}
__device__ __forceinline__ float f2tf32f(float x) {
    return __uint_as_float(f2tf32(x));
}

// ---------------------------------------------------------------------------
// K0: aq = act(addresses), si = sigmoid(interpolation_logits)
// ---------------------------------------------------------------------------
__global__ void prep_kernel(const float* __restrict__ addresses,
                            const float* __restrict__ interp) {
    int i = blockIdx.x * blockDim.x + threadIdx.x;
    if (i < NM * DMEM) {
        g_aq[i] = actf(addresses[i]);
        g_si[i] = sigm(interp[i]);
    }
}

// ---------------------------------------------------------------------------
// K1: fused projection GEMMs via mma.sync tf32 (m16n8k8)
//   BM=64 BN=64 BK=32, 256 threads (8 warps, 2x4), warp tile 32x16.
//   blockIdx.x <  16: g_ak = act(key @ W_key + b_key),    N=1024
//   blockIdx.x >= 16: g_v  =      values @ W_val + b_val, N=2048
// ---------------------------------------------------------------------------
#define BM 64
#define BN 64
#define BK 32
#define PADA 36
#define PADB 72

__global__ __launch_bounds__(256) void proj_mma_kernel(
    const float* __restrict__ key, const float* __restrict__ values,
    const float* __restrict__ W_key, const float* __restrict__ b_key,
    const float* __restrict__ W_val, const float* __restrict__ b_val)
{
    const float *A, *W, *bias;
    float* C;
    int N, doact;
    int bx = blockIdx.x;
    if (bx < KPROJ_N / BN) { A = key;    W = W_key; bias = b_key; C = g_ak; N = KPROJ_N; doact = 1; }
    else { bx -= KPROJ_N / BN; A = values; W = W_val; bias = b_val; C = g_v; N = VPROJ_N; doact = 0; }

    __shared__ float As[BM][PADA];   // [m][k], tf32-rounded
    __shared__ float Bs[BK][PADB];   // [k][n], tf32-rounded

    int t = threadIdx.x;
    int lane = t & 31;
    int warp = t >> 5;
    int g  = lane >> 2;       // group id 0..7
    int tg = lane & 3;        // thread-in-group 0..3
    int wm = (warp & 1) * 32; // warp m-offset
    int wn = (warp >> 1) * 16;// warp n-offset
    int bm0 = blockIdx.y * BM;
    int bn0 = bx * BN;

    float acc[2][2][4];
    #pragma unroll
    for (int i = 0; i < 2; i++)
        #pragma unroll
        for (int j = 0; j < 2; j++)
            #pragma unroll
            for (int r = 0; r < 4; r++) acc[i][j][r] = 0.f;

    // global tile load indexing (64x32 A floats = 512 float4; 32x64 B = 512 float4)
    int ar0 = t >> 3,        ac0 = (t & 7) * 4;     // A rows 0..31
    int ar1 = ar0 + 32;                              // A rows 32..63
    int bk0 = t >> 4,        bn4 = (t & 15) * 4;    // B k 0..15
    // second B half: k + 16

    const float* Ab = A + (size_t)bm0 * DMODEL;

    float4 aR0 = *(const float4*)(Ab + (size_t)ar0 * DMODEL + ac0);
    float4 aR1 = *(const float4*)(Ab + (size_t)ar1 * DMODEL + ac0);
    float4 bR0 = *(const float4*)(W + (size_t)bk0 * N + bn0 + bn4);
    float4 bR1 = *(const float4*)(W + (size_t)(bk0 + 16) * N + bn0 + bn4);

    const int NKT = DMODEL / BK;   // 64
    for (int kt = 0; kt < NKT; kt++) {
        __syncthreads();
        // store (tf32-rounded) into smem
        As[ar0][ac0 + 0] = f2tf32f(aR0.x);
        As[ar0][ac0 + 1] = f2tf32f(aR0.y);
        As[ar0][ac0 + 2] = f2tf32f(aR0.z);
        As[ar0][ac0 + 3] = f2tf32f(aR0.w);
        As[ar1][ac0 + 0] = f2tf32f(aR1.x);
        As[ar1][ac0 + 1] = f2tf32f(aR1.y);
        As[ar1][ac0 + 2] = f2tf32f(aR1.z);
        As[ar1][ac0 + 3] = f2tf32f(aR1.w);
        float4 c0 = {f2tf32f(bR0.x), f2tf32f(bR0.y), f2tf32f(bR0.z), f2tf32f(bR0.w)};
        float4 c1 = {f2tf32f(bR1.x), f2tf32f(bR1.y), f2tf32f(bR1.z), f2tf32f(bR1.w)};
        *(float4*)&Bs[bk0][bn4]      = c0;
        *(float4*)&Bs[bk0 + 16][bn4] = c1;
        __syncthreads();

        if (kt + 1 < NKT) {
            int k0 = (kt + 1) * BK;
            aR0 = *(const float4*)(Ab + (size_t)ar0 * DMODEL + k0 + ac0);
            aR1 = *(const float4*)(Ab + (size_t)ar1 * DMODEL + k0 + ac0);
            bR0 = *(const float4*)(W + (size_t)(k0 + bk0) * N + bn0 + bn4);
            bR1 = *(const float4*)(W + (size_t)(k0 + bk0 + 16) * N + bn0 + bn4);
        }

        #pragma unroll
        for (int ks = 0; ks < 4; ks++) {
            int kk = ks * 8;
            unsigned a[2][4], b[2][2];
            #pragma unroll
            for (int ms = 0; ms < 2; ms++) {
                int m = wm + ms * 16 + g;
                a[ms][0] = __float_as_uint(As[m    ][kk + tg    ]);
                a[ms][1] = __float_as_uint(As[m + 8][kk + tg    ]);
                a[ms][2] = __float_as_uint(As[m    ][kk + tg + 4]);
                a[ms][3] = __float_as_uint(As[m + 8][kk + tg + 4]);
            }
            #pragma unroll
            for (int ns = 0; ns < 2; ns++) {
                int n = wn + ns * 8 + g;
                b[ns][0] = __float_as_uint(Bs[kk + tg    ][n]);
                b[ns][1] = __float_as_uint(Bs[kk + tg + 4][n]);
            }
            #pragma unroll
            for (int ms = 0; ms < 2; ms++)
                #pragma unroll
                for (int ns = 0; ns < 2; ns++) {
                    asm volatile(
                        "mma.sync.aligned.m16n8k8.row.col.f32.tf32.tf32.f32 "
                        "{%0,%1,%2,%3}, {%4,%5,%6,%7}, {%8,%9}, {%0,%1,%2,%3};\n"
                        : "+f"(acc[ms][ns][0]), "+f"(acc[ms][ns][1]),
                          "+f"(acc[ms][ns][2]), "+f"(acc[ms][ns][3])
                        : "r"(a[ms][0]), "r"(a[ms][1]), "r"(a[ms][2]), "r"(a[ms][3]),
                          "r"(b[ns][0]), "r"(b[ns][1]));
                }
        }
    }

    // epilogue: c0,c1 -> (row g, col 2tg..2tg+1); c2,c3 -> (row g+8, same cols)
    #pragma unroll
    for (int ms = 0; ms < 2; ms++) {
        int row0 = bm0 + wm + ms * 16 + g;
        #pragma unroll
        for (int ns = 0; ns < 2; ns++) {
            int col = bn0 + wn + ns * 8 + 2 * tg;
            float b0 = bias[col], b1 = bias[col + 1];
            float o0 = acc[ms][ns][0] + b0;
            float o1 = acc[ms][ns][1] + b1;
            float o2 = acc[ms][ns][2] + b0;
            float o3 = acc[ms][ns][3] + b1;
            if (doact) { o0 = actf(o0); o1 = actf(o1); o2 = actf(o2); o3 = actf(o3); }
            float2 lo = {o0, o1}, hi = {o2, o3};
            *(float2*)(C + (size_t)row0 * N + col)       = lo;
            *(float2*)(C + (size_t)(row0 + 8) * N + col) = hi;
        }
    }
}

// ---------------------------------------------------------------------------
// K2: S[b,m,h] = sum_d aq[m,d] * ak[b,h,d]
// ---------------------------------------------------------------------------
__global__ __launch_bounds__(256) void s_kernel() {
    int b  = blockIdx.y;
    int m0 = blockIdx.x * 32;
    __shared__ float ak_s[8][132];
    __shared__ float aq_s[32][132];
    int t = threadIdx.x;
    {
        int h = t >> 5, d4 = (t & 31) * 4;
        float4 v = *(const float4*)&g_ak[b * KPROJ_N + h * DMEM + d4];
        *(float4*)&ak_s[h][d4] = v;
    }
    #pragma unroll
    for (int i = 0; i < 4; i++) {
        int idx = t + i * 256;
        int ml = idx >> 5, d4 = (idx & 31) * 4;
        float4 v = *(const float4*)&g_aq[(m0 + ml) * DMEM + d4];
        *(float4*)&aq_s[ml][d4] = v;
    }
    __syncthreads();
    int ml = t >> 3, h = t & 7;
    float s = 0.f;
    #pragma unroll
    for (int d4 = 0; d4 < 32; d4++) {
        float4 a = *(const float4*)&aq_s[ml][d4 * 4];
        float4 k = *(const float4*)&ak_s[h][d4 * 4];
        s += a.x * k.x + a.y * k.y + a.z * k.z + a.w * k.w;
    }
    g_S[(b * NM + m0 + ml) * NH + h] = s;
}

// ---------------------------------------------------------------------------
// K3: epilogue (memory-bound). Register-thrifty: lower half (write logits)
// first -> wf, then upper half (update) reusing the accumulator registers.
// Early global loads for MLP; launch_bounds caps regs for 5 CTAs/SM.
// ---------------------------------------------------------------------------
__global__ __launch_bounds__(256, 5) void epilogue_kernel(
    const float* __restrict__ memories, const float* __restrict__ write_mass,
    const unsigned char* __restrict__ batch_mask, float* __restrict__ out)
{
    int b  = blockIdx.y;
    int m0 = blockIdx.x * 8;
    __shared__ float4 v_s[NH * 64];    // v[h][e4]
    __shared__ float  S_s[8][9];
    int t = threadIdx.x;
    int ml = t >> 5, d4 = t & 31;
    int m  = m0 + ml;
    size_t base = ((size_t)b * NM + m) * DMEM + d4 * 4;

    // issue streaming loads early
    float4 mem = *(const float4*)&memories[base];
    float4 wm4 = *(const float4*)&write_mass[base];
    float4 si  = *(const float4*)&g_si[m * DMEM + d4 * 4];
    unsigned char msk = batch_mask[b];

    #pragma unroll
    for (int i = 0; i < 2; i++) {
        int idx = t + i * 256;
        v_s[idx] = ((const float4*)(g_v + (size_t)b * VPROJ_N))[idx];
    }
    if (t < 64)
        S_s[t >> 3][t & 7] = g_S[((size_t)b * NM + m0) * NH + t];
    __syncthreads();

    float denom = 1e-5f;
    #pragma unroll
    for (int h = 0; h < 8; h++) denom += S_s[ml][h];
    float rd = __fdividef(1.f, denom);

    // lower half: write logits -> write factor
    float4 aL = {0, 0, 0, 0};
    #pragma unroll
    for (int h = 0; h < 8; h++) {
        float s = S_s[ml][h];
        float4 vl = v_s[h * 64 + 32 + d4];
        aL.x = fmaf(s, vl.x, aL.x); aL.y = fmaf(s, vl.y, aL.y);
        aL.z = fmaf(s, vl.z, aL.z); aL.w = fmaf(s, vl.w, aL.w);
    }
    float4 wf;
    wf.x = 0.7f * sigm(aL.x * rd) * si.x;
    wf.y = 0.7f * sigm(aL.y * rd) * si.y;
    wf.z = 0.7f * sigm(aL.z * rd) * si.z;
    wf.w = 0.7f * sigm(aL.w * rd) * si.w;

    // upper half: update
    float4 aU = {0, 0, 0, 0};
    #pragma unroll
    for (int h = 0; h < 8; h++) {
        float s = S_s[ml][h];
        float4 vu = v_s[h * 64 + d4];
        aU.x = fmaf(s, vu.x, aU.x); aU.y = fmaf(s, vu.y, aU.y);
        aU.z = fmaf(s, vu.z, aU.z); aU.w = fmaf(s, vu.w, aU.w);
    }

    float4 om, oa;
    if (msk) {
        om = mem; oa = wm4;
    } else {
        om.x = mem.x + wf.x * (aU.x * rd - mem.x);
        om.y = mem.y + wf.y * (aU.y * rd - mem.y);
        om.z = mem.z + wf.z * (aU.z * rd - mem.z);
        om.w = mem.w + wf.w * (aU.w * rd - mem.w);
        oa.x = wm4.x + wf.x; oa.y = wm4.y + wf.y;
        oa.z = wm4.z + wf.z; oa.w = wm4.w + wf.w;
    }
    *(float4*)&out[base] = om;
    *(float4*)&out[MEM_ELEMS + base] = oa;
}

// ---------------------------------------------------------------------------
extern "C" void kernel_launch(void* const* d_in, const int* in_sizes, int n_in,
                              void* d_out, int out_size) {
    const float* key        = (const float*)d_in[0];
    const float* values     = (const float*)d_in[1];
    const float* memories   = (const float*)d_in[2];
    const float* write_mass = (const float*)d_in[3];
    const unsigned char* batch_mask = (const unsigned char*)d_in[4];
    const float* W_key      = (const float*)d_in[5];
    const float* b_key      = (const float*)d_in[6];
    const float* W_val      = (const float*)d_in[7];
    const float* b_val      = (const float*)d_in[8];
    const float* addresses  = (const float*)d_in[9];
    const float* interp     = (const float*)d_in[10];
    float* out = (float*)d_out;

    prep_kernel<<<256, 256>>>(addresses, interp);
    proj_mma_kernel<<<dim3((KPROJ_N + VPROJ_N) / BN, NB / BM), 256>>>(
        key, values, W_key, b_key, W_val, b_val);
    s_kernel<<<dim3(NM / 32, NB), 256>>>();
    epilogue_kernel<<<dim3(NM / 8, NB), 256>>>(memories, write_mass, batch_mask, out);
}

// round 7
// speedup vs baseline: 1.5583x; 1.1438x over previous
#include <cuda_runtime.h>
#include <math.h>

#define NB 512
#define DMODEL 2048
#define NH 8
#define DMEM 128
#define NM 512
#define KPROJ_N 1024     // H*DMEM
#define VPROJ_N 2048     // 2*H*DMEM
#define MEM_ELEMS (NB*NM*DMEM)

// Scratch (device globals: no allocation allowed)
__device__ float g_ak[NB * KPROJ_N];
__device__ float g_v [NB * VPROJ_N];
__device__ float g_aq[NM * DMEM];
__device__ float g_si[NM * DMEM];
__device__ float g_S [NB * NM * NH];

__device__ __forceinline__ float actf(float x) {
    return x > 0.f ? x + 1.f : __expf(x);   // elu(x)+1
}
__device__ __forceinline__ float sigm(float x) {
    return 1.f / (1.f + __expf(-x));
}
__device__ __forceinline__ unsigned f2tf32(float x) {
    unsigned r; asm("cvt.rna.tf32.f32 %0, %1;" : "=r"(r) : "f"(x)); return r;
}
__device__ __forceinline__ float f2tf32f(float x) {
    return __uint_as_float(f2tf32(x));
}

// ---------------------------------------------------------------------------
// K0: aq = act(addresses), si = sigmoid(interpolation_logits)
// ---------------------------------------------------------------------------
__global__ void prep_kernel(const float* __restrict__ addresses,
                            const float* __restrict__ interp) {
    int i = blockIdx.x * blockDim.x + threadIdx.x;
    if (i < NM * DMEM) {
        g_aq[i] = actf(addresses[i]);
        g_si[i] = sigm(interp[i]);
    }
}

// ---------------------------------------------------------------------------
// K1: fused projection GEMMs via mma.sync tf32 (m16n8k8)
//   BM=64 BN=64 BK=32, 256 threads (8 warps, 2x4), warp tile 32x16.
// ---------------------------------------------------------------------------
#define BM 64
#define BN 64
#define BK 32
#define PADA 36
#define PADB 72

__global__ __launch_bounds__(256) void proj_mma_kernel(
    const float* __restrict__ key, const float* __restrict__ values,
    const float* __restrict__ W_key, const float* __restrict__ b_key,
    const float* __restrict__ W_val, const float* __restrict__ b_val)
{
    const float *A, *W, *bias;
    float* C;
    int N, doact;
    int bx = blockIdx.x;
    if (bx < KPROJ_N / BN) { A = key;    W = W_key; bias = b_key; C = g_ak; N = KPROJ_N; doact = 1; }
    else { bx -= KPROJ_N / BN; A = values; W = W_val; bias = b_val; C = g_v; N = VPROJ_N; doact = 0; }

    __shared__ float As[BM][PADA];   // [m][k], tf32-rounded
    __shared__ float Bs[BK][PADB];   // [k][n], tf32-rounded

    int t = threadIdx.x;
    int lane = t & 31;
    int warp = t >> 5;
    int g  = lane >> 2;       // group id 0..7
    int tg = lane & 3;        // thread-in-group 0..3
    int wm = (warp & 1) * 32; // warp m-offset
    int wn = (warp >> 1) * 16;// warp n-offset
    int bm0 = blockIdx.y * BM;
    int bn0 = bx * BN;

    float acc[2][2][4];
    #pragma unroll
    for (int i = 0; i < 2; i++)
        #pragma unroll
        for (int j = 0; j < 2; j++)
            #pragma unroll
            for (int r = 0; r < 4; r++) acc[i][j][r] = 0.f;

    int ar0 = t >> 3,        ac0 = (t & 7) * 4;     // A rows 0..31
    int ar1 = ar0 + 32;                              // A rows 32..63
    int bk0 = t >> 4,        bn4 = (t & 15) * 4;    // B k 0..15

    const float* Ab = A + (size_t)bm0 * DMODEL;

    float4 aR0 = *(const float4*)(Ab + (size_t)ar0 * DMODEL + ac0);
    float4 aR1 = *(const float4*)(Ab + (size_t)ar1 * DMODEL + ac0);
    float4 bR0 = *(const float4*)(W + (size_t)bk0 * N + bn0 + bn4);
    float4 bR1 = *(const float4*)(W + (size_t)(bk0 + 16) * N + bn0 + bn4);

    const int NKT = DMODEL / BK;   // 64
    for (int kt = 0; kt < NKT; kt++) {
        __syncthreads();
        As[ar0][ac0 + 0] = f2tf32f(aR0.x);
        As[ar0][ac0 + 1] = f2tf32f(aR0.y);
        As[ar0][ac0 + 2] = f2tf32f(aR0.z);
        As[ar0][ac0 + 3] = f2tf32f(aR0.w);
        As[ar1][ac0 + 0] = f2tf32f(aR1.x);
        As[ar1][ac0 + 1] = f2tf32f(aR1.y);
        As[ar1][ac0 + 2] = f2tf32f(aR1.z);
        As[ar1][ac0 + 3] = f2tf32f(aR1.w);
        float4 c0 = {f2tf32f(bR0.x), f2tf32f(bR0.y), f2tf32f(bR0.z), f2tf32f(bR0.w)};
        float4 c1 = {f2tf32f(bR1.x), f2tf32f(bR1.y), f2tf32f(bR1.z), f2tf32f(bR1.w)};
        *(float4*)&Bs[bk0][bn4]      = c0;
        *(float4*)&Bs[bk0 + 16][bn4] = c1;
        __syncthreads();

        if (kt + 1 < NKT) {
            int k0 = (kt + 1) * BK;
            aR0 = *(const float4*)(Ab + (size_t)ar0 * DMODEL + k0 + ac0);
            aR1 = *(const float4*)(Ab + (size_t)ar1 * DMODEL + k0 + ac0);
            bR0 = *(const float4*)(W + (size_t)(k0 + bk0) * N + bn0 + bn4);
            bR1 = *(const float4*)(W + (size_t)(k0 + bk0 + 16) * N + bn0 + bn4);
        }

        #pragma unroll
        for (int ks = 0; ks < 4; ks++) {
            int kk = ks * 8;
            unsigned a[2][4], b[2][2];
            #pragma unroll
            for (int ms = 0; ms < 2; ms++) {
                int m = wm + ms * 16 + g;
                a[ms][0] = __float_as_uint(As[m    ][kk + tg    ]);
                a[ms][1] = __float_as_uint(As[m + 8][kk + tg    ]);
                a[ms][2] = __float_as_uint(As[m    ][kk + tg + 4]);
                a[ms][3] = __float_as_uint(As[m + 8][kk + tg + 4]);
            }
            #pragma unroll
            for (int ns = 0; ns < 2; ns++) {
                int n = wn + ns * 8 + g;
                b[ns][0] = __float_as_uint(Bs[kk + tg    ][n]);
                b[ns][1] = __float_as_uint(Bs[kk + tg + 4][n]);
            }
            #pragma unroll
            for (int ms = 0; ms < 2; ms++)
                #pragma unroll
                for (int ns = 0; ns < 2; ns++) {
                    asm volatile(
                        "mma.sync.aligned.m16n8k8.row.col.f32.tf32.tf32.f32 "
                        "{%0,%1,%2,%3}, {%4,%5,%6,%7}, {%8,%9}, {%0,%1,%2,%3};\n"
                        : "+f"(acc[ms][ns][0]), "+f"(acc[ms][ns][1]),
                          "+f"(acc[ms][ns][2]), "+f"(acc[ms][ns][3])
                        : "r"(a[ms][0]), "r"(a[ms][1]), "r"(a[ms][2]), "r"(a[ms][3]),
                          "r"(b[ns][0]), "r"(b[ns][1]));
                }
        }
    }

    #pragma unroll
    for (int ms = 0; ms < 2; ms++) {
        int row0 = bm0 + wm + ms * 16 + g;
        #pragma unroll
        for (int ns = 0; ns < 2; ns++) {
            int col = bn0 + wn + ns * 8 + 2 * tg;
            float b0 = bias[col], b1 = bias[col + 1];
            float o0 = acc[ms][ns][0] + b0;
            float o1 = acc[ms][ns][1] + b1;
            float o2 = acc[ms][ns][2] + b0;
            float o3 = acc[ms][ns][3] + b1;
            if (doact) { o0 = actf(o0); o1 = actf(o1); o2 = actf(o2); o3 = actf(o3); }
            float2 lo = {o0, o1}, hi = {o2, o3};
            *(float2*)(C + (size_t)row0 * N + col)       = lo;
            *(float2*)(C + (size_t)(row0 + 8) * N + col) = hi;
        }
    }
}

// ---------------------------------------------------------------------------
// K2: S[b,m,h] = sum_d aq[m,d] * ak[b,h,d]
// ---------------------------------------------------------------------------
__global__ __launch_bounds__(256) void s_kernel() {
    int b  = blockIdx.y;
    int m0 = blockIdx.x * 32;
    __shared__ float ak_s[8][132];
    __shared__ float aq_s[32][132];
    int t = threadIdx.x;
    {
        int h = t >> 5, d4 = (t & 31) * 4;
        float4 v = *(const float4*)&g_ak[b * KPROJ_N + h * DMEM + d4];
        *(float4*)&ak_s[h][d4] = v;
    }
    #pragma unroll
    for (int i = 0; i < 4; i++) {
        int idx = t + i * 256;
        int ml = idx >> 5, d4 = (idx & 31) * 4;
        float4 v = *(const float4*)&g_aq[(m0 + ml) * DMEM + d4];
        *(float4*)&aq_s[ml][d4] = v;
    }
    __syncthreads();
    int ml = t >> 3, h = t & 7;
    float s = 0.f;
    #pragma unroll
    for (int d4 = 0; d4 < 32; d4++) {
        float4 a = *(const float4*)&aq_s[ml][d4 * 4];
        float4 k = *(const float4*)&ak_s[h][d4 * 4];
        s += a.x * k.x + a.y * k.y + a.z * k.z + a.w * k.w;
    }
    g_S[(b * NM + m0 + ml) * NH + h] = s;
}

// ---------------------------------------------------------------------------
// K3: epilogue. h-loop outermost, 4 m-rows per thread: each v_s smem read
// feeds 4 rows of FMA -> LDS volume per DRAM byte cut 4x vs round 6
// (which was L1-crossbar-bound at 91.5%). Block covers 32 rows of one b.
// ---------------------------------------------------------------------------
__global__ __launch_bounds__(256) void epilogue_kernel(
    const float* __restrict__ memories, const float* __restrict__ write_mass,
    const unsigned char* __restrict__ batch_mask, float* __restrict__ out)
{
    int b  = blockIdx.y;
    int m0 = blockIdx.x * 32;
    __shared__ float4 v_s[NH * 64];    // v[h][e4], e4 in [0,64)
    __shared__ float  S_s[32][9];      // S for 32 rows, padded
    int t = threadIdx.x;
    int ml = t >> 5;                   // warp id: row group (4 rows each)
    int d4 = t & 31;

    // fill v (8 KB) and S (1 KB)
    #pragma unroll
    for (int i = 0; i < 2; i++) {
        int idx = t + i * 256;
        v_s[idx] = ((const float4*)(g_v + (size_t)b * VPROJ_N))[idx];
    }
    S_s[t >> 3][t & 7] = g_S[((size_t)b * NM + m0) * NH + t];
    __syncthreads();

    unsigned char msk = batch_mask[b];
    int r0 = ml * 4;                   // first of this thread's 4 rows

    float4 aU[4], aL[4];
    float dn[4];
    #pragma unroll
    for (int i = 0; i < 4; i++) {
        aU[i] = make_float4(0.f, 0.f, 0.f, 0.f);
        aL[i] = make_float4(0.f, 0.f, 0.f, 0.f);
        dn[i] = 1e-5f;
    }

    #pragma unroll
    for (int h = 0; h < 8; h++) {
        float4 vu = v_s[h * 64 + d4];
        float4 vl = v_s[h * 64 + 32 + d4];
        #pragma unroll
        for (int i = 0; i < 4; i++) {
            float s = S_s[r0 + i][h];   // warp-uniform broadcast
            dn[i] += s;
            aU[i].x = fmaf(s, vu.x, aU[i].x); aU[i].y = fmaf(s, vu.y, aU[i].y);
            aU[i].z = fmaf(s, vu.z, aU[i].z); aU[i].w = fmaf(s, vu.w, aU[i].w);
            aL[i].x = fmaf(s, vl.x, aL[i].x); aL[i].y = fmaf(s, vl.y, aL[i].y);
            aL[i].z = fmaf(s, vl.z, aL[i].z); aL[i].w = fmaf(s, vl.w, aL[i].w);
        }
    }

    // per-row streaming tail (independent chains; loads get hoisted/batched)
    #pragma unroll
    for (int i = 0; i < 4; i++) {
        int m = m0 + r0 + i;
        size_t base = ((size_t)b * NM + m) * DMEM + d4 * 4;
        float4 mem = *(const float4*)&memories[base];
        float4 wm4 = *(const float4*)&write_mass[base];
        float4 si  = *(const float4*)&g_si[m * DMEM + d4 * 4];

        float rd = __fdividef(1.f, dn[i]);
        float4 wf;
        wf.x = 0.7f * sigm(aL[i].x * rd) * si.x;
        wf.y = 0.7f * sigm(aL[i].y * rd) * si.y;
        wf.z = 0.7f * sigm(aL[i].z * rd) * si.z;
        wf.w = 0.7f * sigm(aL[i].w * rd) * si.w;

        float4 om, oa;
        if (msk) {
            om = mem; oa = wm4;
        } else {
            om.x = mem.x + wf.x * (aU[i].x * rd - mem.x);
            om.y = mem.y + wf.y * (aU[i].y * rd - mem.y);
            om.z = mem.z + wf.z * (aU[i].z * rd - mem.z);
            om.w = mem.w + wf.w * (aU[i].w * rd - mem.w);
            oa.x = wm4.x + wf.x; oa.y = wm4.y + wf.y;
            oa.z = wm4.z + wf.z; oa.w = wm4.w + wf.w;
        }
        *(float4*)&out[base] = om;
        *(float4*)&out[MEM_ELEMS + base] = oa;
    }
}

// ---------------------------------------------------------------------------
extern "C" void kernel_launch(void* const* d_in, const int* in_sizes, int n_in,
                              void* d_out, int out_size) {
    const float* key        = (const float*)d_in[0];
    const float* values     = (const float*)d_in[1];
    const float* memories   = (const float*)d_in[2];
    const float* write_mass = (const float*)d_in[3];
    const unsigned char* batch_mask = (const unsigned char*)d_in[4];
    const float* W_key      = (const float*)d_in[5];
    const float* b_key      = (const float*)d_in[6];
    const float* W_val      = (const float*)d_in[7];
    const float* b_val      = (const float*)d_in[8];
    const float* addresses  = (const float*)d_in[9];
    const float* interp     = (const float*)d_in[10];
    float* out = (float*)d_out;

    prep_kernel<<<256, 256>>>(addresses, interp);
    proj_mma_kernel<<<dim3((KPROJ_N + VPROJ_N) / BN, NB / BM), 256>>>(
        key, values, W_key, b_key, W_val, b_val);
    s_kernel<<<dim3(NM / 32, NB), 256>>>();
    epilogue_kernel<<<dim3(NM / 32, NB), 256>>>(memories, write_mass, batch_mask, out);
}

// round 8
// speedup vs baseline: 1.6181x; 1.0384x over previous
#include <cuda_runtime.h>
#include <math.h>

#define NB 512
#define DMODEL 2048
#define NH 8
#define DMEM 128
#define NM 512
#define KPROJ_N 1024     // H*DMEM
#define VPROJ_N 2048     // 2*H*DMEM
#define MEM_ELEMS (NB*NM*DMEM)

// Scratch (device globals: no allocation allowed)
__device__ float g_ak[NB * KPROJ_N];
__device__ float g_v [NB * VPROJ_N];
__device__ float g_aq[NM * DMEM];
__device__ float g_si[NM * DMEM];
__device__ float g_S [NB * NM * NH];

__device__ __forceinline__ float actf(float x) {
    return x > 0.f ? x + 1.f : __expf(x);   // elu(x)+1
}
__device__ __forceinline__ float sigm(float x) {
    return 1.f / (1.f + __expf(-x));
}
__device__ __forceinline__ unsigned f2tf32(float x) {
    unsigned r; asm("cvt.rna.tf32.f32 %0, %1;" : "=r"(r) : "f"(x)); return r;
}
__device__ __forceinline__ float f2tf32f(float x) {
    return __uint_as_float(f2tf32(x));
}

// ---------------------------------------------------------------------------
// K0: aq = act(addresses), si = sigmoid(interpolation_logits)
// ---------------------------------------------------------------------------
__global__ void prep_kernel(const float* __restrict__ addresses,
                            const float* __restrict__ interp) {
    int i = blockIdx.x * blockDim.x + threadIdx.x;
    if (i < NM * DMEM) {
        g_aq[i] = actf(addresses[i]);
        g_si[i] = sigm(interp[i]);
    }
}

// ---------------------------------------------------------------------------
// K1: fused projection GEMMs via mma.sync tf32 (m16n8k8)
//   BM=64 BN=64 BK=32, 256 threads (8 warps, 2x4), warp tile 32x16.
//   2-stage smem double buffer, ONE __syncthreads per K-iter.
// ---------------------------------------------------------------------------
#define BM 64
#define BN 64
#define BK 32
#define PADA 36
#define PADB 72

__global__ __launch_bounds__(256) void proj_mma_kernel(
    const float* __restrict__ key, const float* __restrict__ values,
    const float* __restrict__ W_key, const float* __restrict__ b_key,
    const float* __restrict__ W_val, const float* __restrict__ b_val)
{
    const float *A, *W, *bias;
    float* C;
    int N, doact;
    int bx = blockIdx.x;
    if (bx < KPROJ_N / BN) { A = key;    W = W_key; bias = b_key; C = g_ak; N = KPROJ_N; doact = 1; }
    else { bx -= KPROJ_N / BN; A = values; W = W_val; bias = b_val; C = g_v; N = VPROJ_N; doact = 0; }

    __shared__ float As[2][BM][PADA];   // [stage][m][k], tf32-rounded
    __shared__ float Bs[2][BK][PADB];   // [stage][k][n], tf32-rounded

    int t = threadIdx.x;
    int lane = t & 31;
    int warp = t >> 5;
    int g  = lane >> 2;       // group id 0..7
    int tg = lane & 3;        // thread-in-group 0..3
    int wm = (warp & 1) * 32; // warp m-offset
    int wn = (warp >> 1) * 16;// warp n-offset
    int bm0 = blockIdx.y * BM;
    int bn0 = bx * BN;

    float acc[2][2][4];
    #pragma unroll
    for (int i = 0; i < 2; i++)
        #pragma unroll
        for (int j = 0; j < 2; j++)
            #pragma unroll
            for (int r = 0; r < 4; r++) acc[i][j][r] = 0.f;

    int ar0 = t >> 3,        ac0 = (t & 7) * 4;     // A rows 0..31
    int ar1 = ar0 + 32;                              // A rows 32..63
    int bk0 = t >> 4,        bn4 = (t & 15) * 4;    // B k 0..15

    const float* Ab = A + (size_t)bm0 * DMODEL;

    float4 aR0, aR1, bR0, bR1;

    // prologue: tile 0 -> regs -> smem stage 0
    aR0 = *(const float4*)(Ab + (size_t)ar0 * DMODEL + ac0);
    aR1 = *(const float4*)(Ab + (size_t)ar1 * DMODEL + ac0);
    bR0 = *(const float4*)(W + (size_t)bk0 * N + bn0 + bn4);
    bR1 = *(const float4*)(W + (size_t)(bk0 + 16) * N + bn0 + bn4);

    As[0][ar0][ac0 + 0] = f2tf32f(aR0.x);
    As[0][ar0][ac0 + 1] = f2tf32f(aR0.y);
    As[0][ar0][ac0 + 2] = f2tf32f(aR0.z);
    As[0][ar0][ac0 + 3] = f2tf32f(aR0.w);
    As[0][ar1][ac0 + 0] = f2tf32f(aR1.x);
    As[0][ar1][ac0 + 1] = f2tf32f(aR1.y);
    As[0][ar1][ac0 + 2] = f2tf32f(aR1.z);
    As[0][ar1][ac0 + 3] = f2tf32f(aR1.w);
    {
        float4 c0 = {f2tf32f(bR0.x), f2tf32f(bR0.y), f2tf32f(bR0.z), f2tf32f(bR0.w)};
        float4 c1 = {f2tf32f(bR1.x), f2tf32f(bR1.y), f2tf32f(bR1.z), f2tf32f(bR1.w)};
        *(float4*)&Bs[0][bk0][bn4]      = c0;
        *(float4*)&Bs[0][bk0 + 16][bn4] = c1;
    }
    __syncthreads();

    const int NKT = DMODEL / BK;   // 64
    int buf = 0;
    for (int kt = 0; kt < NKT; kt++) {
        // issue global loads for next tile before computing on current
        if (kt + 1 < NKT) {
            int k0 = (kt + 1) * BK;
            aR0 = *(const float4*)(Ab + (size_t)ar0 * DMODEL + k0 + ac0);
            aR1 = *(const float4*)(Ab + (size_t)ar1 * DMODEL + k0 + ac0);
            bR0 = *(const float4*)(W + (size_t)(k0 + bk0) * N + bn0 + bn4);
            bR1 = *(const float4*)(W + (size_t)(k0 + bk0 + 16) * N + bn0 + bn4);
        }

        #pragma unroll
        for (int ks = 0; ks < 4; ks++) {
            int kk = ks * 8;
            unsigned a[2][4], b[2][2];
            #pragma unroll
            for (int ms = 0; ms < 2; ms++) {
                int m = wm + ms * 16 + g;
                a[ms][0] = __float_as_uint(As[buf][m    ][kk + tg    ]);
                a[ms][1] = __float_as_uint(As[buf][m + 8][kk + tg    ]);
                a[ms][2] = __float_as_uint(As[buf][m    ][kk + tg + 4]);
                a[ms][3] = __float_as_uint(As[buf][m + 8][kk + tg + 4]);
            }
            #pragma unroll
            for (int ns = 0; ns < 2; ns++) {
                int n = wn + ns * 8 + g;
                b[ns][0] = __float_as_uint(Bs[buf][kk + tg    ][n]);
                b[ns][1] = __float_as_uint(Bs[buf][kk + tg + 4][n]);
            }
            #pragma unroll
            for (int ms = 0; ms < 2; ms++)
                #pragma unroll
                for (int ns = 0; ns < 2; ns++) {
                    asm volatile(
                        "mma.sync.aligned.m16n8k8.row.col.f32.tf32.tf32.f32 "
                        "{%0,%1,%2,%3}, {%4,%5,%6,%7}, {%8,%9}, {%0,%1,%2,%3};\n"
                        : "+f"(acc[ms][ns][0]), "+f"(acc[ms][ns][1]),
                          "+f"(acc[ms][ns][2]), "+f"(acc[ms][ns][3])
                        : "r"(a[ms][0]), "r"(a[ms][1]), "r"(a[ms][2]), "r"(a[ms][3]),
                          "r"(b[ns][0]), "r"(b[ns][1]));
                }
        }

        if (kt + 1 < NKT) {
            int nb = buf ^ 1;
            As[nb][ar0][ac0 + 0] = f2tf32f(aR0.x);
            As[nb][ar0][ac0 + 1] = f2tf32f(aR0.y);
            As[nb][ar0][ac0 + 2] = f2tf32f(aR0.z);
            As[nb][ar0][ac0 + 3] = f2tf32f(aR0.w);
            As[nb][ar1][ac0 + 0] = f2tf32f(aR1.x);
            As[nb][ar1][ac0 + 1] = f2tf32f(aR1.y);
            As[nb][ar1][ac0 + 2] = f2tf32f(aR1.z);
            As[nb][ar1][ac0 + 3] = f2tf32f(aR1.w);
            float4 c0 = {f2tf32f(bR0.x), f2tf32f(bR0.y), f2tf32f(bR0.z), f2tf32f(bR0.w)};
            float4 c1 = {f2tf32f(bR1.x), f2tf32f(bR1.y), f2tf32f(bR1.z), f2tf32f(bR1.w)};
            *(float4*)&Bs[nb][bk0][bn4]      = c0;
            *(float4*)&Bs[nb][bk0 + 16][bn4] = c1;
            __syncthreads();
            buf = nb;
        }
    }

    #pragma unroll
    for (int ms = 0; ms < 2; ms++) {
        int row0 = bm0 + wm + ms * 16 + g;
        #pragma unroll
        for (int ns = 0; ns < 2; ns++) {
            int col = bn0 + wn + ns * 8 + 2 * tg;
            float b0 = bias[col], b1 = bias[col + 1];
            float o0 = acc[ms][ns][0] + b0;
            float o1 = acc[ms][ns][1] + b1;
            float o2 = acc[ms][ns][2] + b0;
            float o3 = acc[ms][ns][3] + b1;
            if (doact) { o0 = actf(o0); o1 = actf(o1); o2 = actf(o2); o3 = actf(o3); }
            float2 lo = {o0, o1}, hi = {o2, o3};
            *(float2*)(C + (size_t)row0 * N + col)       = lo;
            *(float2*)(C + (size_t)(row0 + 8) * N + col) = hi;
        }
    }
}

// ---------------------------------------------------------------------------
// K2: S[b,m,h] = sum_d aq[m,d] * ak[b,h,d]
// ---------------------------------------------------------------------------
__global__ __launch_bounds__(256) void s_kernel() {
    int b  = blockIdx.y;
    int m0 = blockIdx.x * 32;
    __shared__ float ak_s[8][132];
    __shared__ float aq_s[32][132];
    int t = threadIdx.x;
    {
        int h = t >> 5, d4 = (t & 31) * 4;
        float4 v = *(const float4*)&g_ak[b * KPROJ_N + h * DMEM + d4];
        *(float4*)&ak_s[h][d4] = v;
    }
    #pragma unroll
    for (int i = 0; i < 4; i++) {
        int idx = t + i * 256;
        int ml = idx >> 5, d4 = (idx & 31) * 4;
        float4 v = *(const float4*)&g_aq[(m0 + ml) * DMEM + d4];
        *(float4*)&aq_s[ml][d4] = v;
    }
    __syncthreads();
    int ml = t >> 3, h = t & 7;
    float s = 0.f;
    #pragma unroll
    for (int d4 = 0; d4 < 32; d4++) {
        float4 a = *(const float4*)&aq_s[ml][d4 * 4];
        float4 k = *(const float4*)&ak_s[h][d4 * 4];
        s += a.x * k.x + a.y * k.y + a.z * k.z + a.w * k.w;
    }
    g_S[(b * NM + m0 + ml) * NH + h] = s;
}

// ---------------------------------------------------------------------------
// K3: epilogue. h-loop outermost, 4 m-rows/thread (LDS amortized 4x), and
// ALL 12 streaming LDG.128 hoisted to the top so their latency is absorbed
// by the compute phase (R7 showed DRAM=52.5% latency-exposed).
// ---------------------------------------------------------------------------
__global__ __launch_bounds__(256) void epilogue_kernel(
    const float* __restrict__ memories, const float* __restrict__ write_mass,
    const unsigned char* __restrict__ batch_mask, float* __restrict__ out)
{
    int b  = blockIdx.y;
    int m0 = blockIdx.x * 32;
    __shared__ float4 v_s[NH * 64];    // v[h][e4], e4 in [0,64)
    __shared__ float  S_s[32][9];      // S for 32 rows, padded
    int t = threadIdx.x;
    int ml = t >> 5;                   // warp id: row group (4 rows each)
    int d4 = t & 31;
    int r0 = ml * 4;

    // ---- streaming loads issued FIRST (12 independent LDG.128) ----
    float4 mem[4], wm4[4], si4[4];
    #pragma unroll
    for (int i = 0; i < 4; i++) {
        int m = m0 + r0 + i;
        size_t base = ((size_t)b * NM + m) * DMEM + d4 * 4;
        mem[i] = *(const float4*)&memories[base];
        wm4[i] = *(const float4*)&write_mass[base];
        si4[i] = *(const float4*)&g_si[m * DMEM + d4 * 4];
    }
    unsigned char msk = batch_mask[b];

    // fill v (8 KB) and S (1 KB)
    #pragma unroll
    for (int i = 0; i < 2; i++) {
        int idx = t + i * 256;
        v_s[idx] = ((const float4*)(g_v + (size_t)b * VPROJ_N))[idx];
    }
    S_s[t >> 3][t & 7] = g_S[((size_t)b * NM + m0) * NH + t];
    __syncthreads();

    float4 aU[4], aL[4];
    float dn[4];
    #pragma unroll
    for (int i = 0; i < 4; i++) {
        aU[i] = make_float4(0.f, 0.f, 0.f, 0.f);
        aL[i] = make_float4(0.f, 0.f, 0.f, 0.f);
        dn[i] = 1e-5f;
    }

    #pragma unroll
    for (int h = 0; h < 8; h++) {
        float4 vu = v_s[h * 64 + d4];
        float4 vl = v_s[h * 64 + 32 + d4];
        #pragma unroll
        for (int i = 0; i < 4; i++) {
            float s = S_s[r0 + i][h];   // warp-uniform broadcast
            dn[i] += s;
            aU[i].x = fmaf(s, vu.x, aU[i].x); aU[i].y = fmaf(s, vu.y, aU[i].y);
            aU[i].z = fmaf(s, vu.z, aU[i].z); aU[i].w = fmaf(s, vu.w, aU[i].w);
            aL[i].x = fmaf(s, vl.x, aL[i].x); aL[i].y = fmaf(s, vl.y, aL[i].y);
            aL[i].z = fmaf(s, vl.z, aL[i].z); aL[i].w = fmaf(s, vl.w, aL[i].w);
        }
    }

    #pragma unroll
    for (int i = 0; i < 4; i++) {
        int m = m0 + r0 + i;
        size_t base = ((size_t)b * NM + m) * DMEM + d4 * 4;

        float rd = __fdividef(1.f, dn[i]);
        float4 wf;
        wf.x = 0.7f * sigm(aL[i].x * rd) * si4[i].x;
        wf.y = 0.7f * sigm(aL[i].y * rd) * si4[i].y;
        wf.z = 0.7f * sigm(aL[i].z * rd) * si4[i].z;
        wf.w = 0.7f * sigm(aL[i].w * rd) * si4[i].w;

        float4 om, oa;
        if (msk) {
            om = mem[i]; oa = wm4[i];
        } else {
            om.x = mem[i].x + wf.x * (aU[i].x * rd - mem[i].x);
            om.y = mem[i].y + wf.y * (aU[i].y * rd - mem[i].y);
            om.z = mem[i].z + wf.z * (aU[i].z * rd - mem[i].z);
            om.w = mem[i].w + wf.w * (aU[i].w * rd - mem[i].w);
            oa.x = wm4[i].x + wf.x; oa.y = wm4[i].y + wf.y;
            oa.z = wm4[i].z + wf.z; oa.w = wm4[i].w + wf.w;
        }
        *(float4*)&out[base] = om;
        *(float4*)&out[MEM_ELEMS + base] = oa;
    }
}

// ---------------------------------------------------------------------------
extern "C" void kernel_launch(void* const* d_in, const int* in_sizes, int n_in,
                              void* d_out, int out_size) {
    const float* key        = (const float*)d_in[0];
    const float* values     = (const float*)d_in[1];
    const float* memories   = (const float*)d_in[2];
    const float* write_mass = (const float*)d_in[3];
    const unsigned char* batch_mask = (const unsigned char*)d_in[4];
    const float* W_key      = (const float*)d_in[5];
    const float* b_key      = (const float*)d_in[6];
    const float* W_val      = (const float*)d_in[7];
    const float* b_val      = (const float*)d_in[8];
    const float* addresses  = (const float*)d_in[9];
    const float* interp     = (const float*)d_in[10];
    float* out = (float*)d_out;

    prep_kernel<<<256, 256>>>(addresses, interp);
    proj_mma_kernel<<<dim3((KPROJ_N + VPROJ_N) / BN, NB / BM), 256>>>(
        key, values, W_key, b_key, W_val, b_val);
    s_kernel<<<dim3(NM / 32, NB), 256>>>();
    epilogue_kernel<<<dim3(NM / 32, NB), 256>>>(memories, write_mass, batch_mask, out);
}